// round 4
// baseline (speedup 1.0000x reference)
#include <cuda_runtime.h>
#include <cstdint>

#define D_DIM 512
#define QMAX  2048

// ---------------- scratch (device globals; no allocation allowed) ----------
__device__ float g_d2[(size_t)QMAX * 100000];   // full [Q][N] squared distances
__device__ float g_x2[QMAX];
__device__ float g_t2[100032];

// ---------------- kernel 0: row squared-norms -------------------------------
__global__ void norms_kernel(const float* __restrict__ M, int rows, int which) {
    int warp = (blockIdx.x * blockDim.x + threadIdx.x) >> 5;
    int lane = threadIdx.x & 31;
    if (warp >= rows) return;
    const float4* row = reinterpret_cast<const float4*>(M + (size_t)warp * D_DIM);
    float s = 0.f;
#pragma unroll
    for (int j = 0; j < (D_DIM / 4) / 32; ++j) {
        float4 v = row[lane + j * 32];
        s += v.x * v.x + v.y * v.y + v.z * v.z + v.w * v.w;
    }
#pragma unroll
    for (int o = 16; o; o >>= 1) s += __shfl_xor_sync(0xffffffffu, s, o);
    if (lane == 0) {
        if (which) g_t2[warp] = s; else g_x2[warp] = s;
    }
}

// ---------------- kernel 1: tiled fp32 GEMM -> d2 ---------------------------
// d2[q][n] = x2[q] + t2[n] - 2 * dot(X[q], T[n])
// 128x128 tile, BK=16, 256 threads, 8x8 register microtile.
#define BM 128
#define BN 128
#define BK 16

__global__ __launch_bounds__(256, 2) void dist_gemm(
    const float* __restrict__ X, const float* __restrict__ T, int N, int Q)
{
    __shared__ float As[BK][BM];
    __shared__ float Bs[BK][BN];

    const int tid = threadIdx.x;
    const int tx = tid & 15;        // target sub-tile (8 cols)
    const int ty = tid >> 4;        // query  sub-tile (8 rows)
    const int bq = blockIdx.y * BM;
    const int bn = blockIdx.x * BN;

    // loader mapping: each thread loads 8 contiguous floats (2 float4) of one row
    const int lrow = tid >> 1;            // 0..127
    const int lk   = (tid & 1) * 8;       // 0 or 8

    const int arow = bq + lrow;
    const int brow = bn + lrow;
    const bool avalid = (arow < Q);
    const bool bvalid = (brow < N);
    const float* aptr = X + (size_t)(avalid ? arow : 0) * D_DIM + lk;
    const float* bptr = T + (size_t)(bvalid ? brow : 0) * D_DIM + lk;

    float acc[8][8];
#pragma unroll
    for (int i = 0; i < 8; ++i)
#pragma unroll
        for (int j = 0; j < 8; ++j) acc[i][j] = 0.f;

    for (int k0 = 0; k0 < D_DIM; k0 += BK) {
        float4 a0 = make_float4(0.f,0.f,0.f,0.f), a1 = a0, b0 = a0, b1 = a0;
        if (avalid) {
            a0 = *reinterpret_cast<const float4*>(aptr + k0);
            a1 = *reinterpret_cast<const float4*>(aptr + k0 + 4);
        }
        if (bvalid) {
            b0 = *reinterpret_cast<const float4*>(bptr + k0);
            b1 = *reinterpret_cast<const float4*>(bptr + k0 + 4);
        }
        As[lk+0][lrow]=a0.x; As[lk+1][lrow]=a0.y; As[lk+2][lrow]=a0.z; As[lk+3][lrow]=a0.w;
        As[lk+4][lrow]=a1.x; As[lk+5][lrow]=a1.y; As[lk+6][lrow]=a1.z; As[lk+7][lrow]=a1.w;
        Bs[lk+0][lrow]=b0.x; Bs[lk+1][lrow]=b0.y; Bs[lk+2][lrow]=b0.z; Bs[lk+3][lrow]=b0.w;
        Bs[lk+4][lrow]=b1.x; Bs[lk+5][lrow]=b1.y; Bs[lk+6][lrow]=b1.z; Bs[lk+7][lrow]=b1.w;
        __syncthreads();

#pragma unroll
        for (int k = 0; k < BK; ++k) {
            float4 av0 = *reinterpret_cast<const float4*>(&As[k][ty * 8]);
            float4 av1 = *reinterpret_cast<const float4*>(&As[k][ty * 8 + 4]);
            float4 bv0 = *reinterpret_cast<const float4*>(&Bs[k][tx * 8]);
            float4 bv1 = *reinterpret_cast<const float4*>(&Bs[k][tx * 8 + 4]);
            float ar[8] = {av0.x, av0.y, av0.z, av0.w, av1.x, av1.y, av1.z, av1.w};
            float br[8] = {bv0.x, bv0.y, bv0.z, bv0.w, bv1.x, bv1.y, bv1.z, bv1.w};
#pragma unroll
            for (int i = 0; i < 8; ++i)
#pragma unroll
                for (int j = 0; j < 8; ++j) acc[i][j] += ar[i] * br[j];
        }
        __syncthreads();
    }

    // epilogue: d2 = x2 + t2 - 2*dot
#pragma unroll
    for (int i = 0; i < 8; ++i) {
        int q = bq + ty * 8 + i;
        if (q >= Q) continue;
        float qn = g_x2[q];
#pragma unroll
        for (int h = 0; h < 2; ++h) {
            int n0 = bn + tx * 8 + h * 4;
            if (n0 + 3 < N) {
                float4 o;
                o.x = qn + g_t2[n0+0] - 2.f * acc[i][h*4+0];
                o.y = qn + g_t2[n0+1] - 2.f * acc[i][h*4+1];
                o.z = qn + g_t2[n0+2] - 2.f * acc[i][h*4+2];
                o.w = qn + g_t2[n0+3] - 2.f * acc[i][h*4+3];
                *reinterpret_cast<float4*>(&g_d2[(size_t)q * N + n0]) = o;
            } else {
#pragma unroll
                for (int j = 0; j < 4; ++j) {
                    int n = n0 + j;
                    if (n < N) g_d2[(size_t)q * N + n] = qn + g_t2[n] - 2.f * acc[i][h*4+j];
                }
            }
        }
    }
}

// ---------------- kernel 2: per-query top-5 + outputs -----------------------
// out layout (float32): [ dists Q*5 | inds Q*5 | pred 5*Q (pred[j][q]) ]
#define TKT 256
#define KSEL 5

__global__ __launch_bounds__(TKT) void topk_kernel(
    const int* __restrict__ labels, float* __restrict__ out,
    int N, int Q, int out_size)
{
    const int q = blockIdx.x;
    const float* row = g_d2 + (size_t)q * N;

    float bd[KSEL];
    int   bi[KSEL];
#pragma unroll
    for (int j = 0; j < KSEL; ++j) { bd[j] = 3.4e38f; bi[j] = 0x7fffffff; }

    for (int n = threadIdx.x; n < N; n += TKT) {
        float d = row[n];
        if (d < bd[KSEL - 1] || (d == bd[KSEL - 1] && n < bi[KSEL - 1])) {
            int p = KSEL - 1;
            while (p > 0 && (d < bd[p - 1] || (d == bd[p - 1] && n < bi[p - 1]))) {
                bd[p] = bd[p - 1]; bi[p] = bi[p - 1]; --p;
            }
            bd[p] = d; bi[p] = n;
        }
    }

    __shared__ float sd[TKT * KSEL];
    __shared__ int   si[TKT * KSEL];
#pragma unroll
    for (int j = 0; j < KSEL; ++j) {
        sd[threadIdx.x * KSEL + j] = bd[j];
        si[threadIdx.x * KSEL + j] = bi[j];
    }
    __syncthreads();

    if (threadIdx.x == 0) {
        float fd[KSEL]; int fi[KSEL];
#pragma unroll
        for (int j = 0; j < KSEL; ++j) { fd[j] = 3.4e38f; fi[j] = 0x7fffffff; }
        for (int t = 0; t < TKT * KSEL; ++t) {
            float d = sd[t]; int i = si[t];
            if (d < fd[KSEL - 1] || (d == fd[KSEL - 1] && i < fi[KSEL - 1])) {
                int p = KSEL - 1;
                while (p > 0 && (d < fd[p - 1] || (d == fd[p - 1] && i < fi[p - 1]))) {
                    fd[p] = fd[p - 1]; fi[p] = fi[p - 1]; --p;
                }
                fd[p] = d; fi[p] = i;
            }
        }
        const int Q5 = Q * KSEL;
#pragma unroll
        for (int j = 0; j < KSEL; ++j) {
            float dist = sqrtf(fmaxf(fd[j], 0.f));
            int   idx  = fi[j];
            int o0 = q * KSEL + j;                 // dists
            int o1 = Q5 + q * KSEL + j;            // inds
            int o2 = 2 * Q5 + j * Q + q;           // pred[j][q]
            if (o0 < out_size) out[o0] = dist;
            if (o1 < out_size) out[o1] = (float)idx;
            if (o2 < out_size) out[o2] = (float)(labels[idx]);
        }
    }
}

// ---------------- launch ----------------------------------------------------
extern "C" void kernel_launch(void* const* d_in, const int* in_sizes, int n_in,
                              void* d_out, int out_size)
{
    const float* X      = (const float*)d_in[0];
    const float* T      = (const float*)d_in[1];
    const int*   labels = (const int*)d_in[2];   // int64 in reference, delivered as int32
    const int Q = in_sizes[0] / D_DIM;
    const int N = in_sizes[2];

    norms_kernel<<<(Q + 7) / 8, 256>>>(X, Q, 0);
    norms_kernel<<<(N + 7) / 8, 256>>>(T, N, 1);

    dim3 grid((N + BN - 1) / BN, (Q + BM - 1) / BM);
    dist_gemm<<<grid, 256>>>(X, T, N, Q);

    topk_kernel<<<Q, TKT>>>(labels, (float*)d_out, N, Q, out_size);
}

// round 7
// speedup vs baseline: 4.0297x; 4.0297x over previous
#include <cuda_runtime.h>
#include <cuda_bf16.h>
#include <cstdint>

#define D_DIM 512
#define QMAX  2048
#define NPAD  100096   // 782 * 128

// ---------------- scratch (device globals; no allocation allowed) -----------
__device__ __align__(16) float g_d2[(size_t)QMAX * 100000];  // approx d2 (bf16 GEMM)
__device__ float g_x2[QMAX];
__device__ float g_t2[NPAD];
__device__ __align__(256) __nv_bfloat16 g_xb[(size_t)QMAX * D_DIM];
__device__ __align__(256) __nv_bfloat16 g_tb[(size_t)NPAD * D_DIM];

// ---------------- kernel: fused fp32->bf16 convert + row norms --------------
__global__ void convert_norm(const float* __restrict__ src, int rows_valid,
                             int rows_total, int which)
{
    int gw   = (blockIdx.x * blockDim.x + threadIdx.x) >> 5;
    int lane = threadIdx.x & 31;
    if (gw >= rows_total) return;
    __nv_bfloat162* dst =
        reinterpret_cast<__nv_bfloat162*>(which ? g_tb : g_xb) + (size_t)gw * (D_DIM / 2);
    if (gw < rows_valid) {
        const float4* r4 = reinterpret_cast<const float4*>(src + (size_t)gw * D_DIM);
        float s = 0.f;
#pragma unroll
        for (int j = 0; j < 4; ++j) {
            float4 v = r4[lane + j * 32];
            s += v.x * v.x + v.y * v.y + v.z * v.z + v.w * v.w;
            dst[(lane + j * 32) * 2 + 0] = __floats2bfloat162_rn(v.x, v.y);
            dst[(lane + j * 32) * 2 + 1] = __floats2bfloat162_rn(v.z, v.w);
        }
#pragma unroll
        for (int o = 16; o; o >>= 1) s += __shfl_xor_sync(0xffffffffu, s, o);
        if (lane == 0) { if (which) g_t2[gw] = s; else g_x2[gw] = s; }
    } else {
        __nv_bfloat162 z = __floats2bfloat162_rn(0.f, 0.f);
#pragma unroll
        for (int j = 0; j < 4; ++j) {
            dst[(lane + j * 32) * 2 + 0] = z;
            dst[(lane + j * 32) * 2 + 1] = z;
        }
        if (lane == 0 && which) g_t2[gw] = 3.0e38f;
    }
}

// ---------------- mma.sync m16n8k16 bf16 wrapper (portable HMMA) -------------
__device__ __forceinline__ void mma16816(float* c, const uint32_t* a, const uint32_t* b) {
    asm volatile(
        "mma.sync.aligned.m16n8k16.row.col.f32.bf16.bf16.f32 "
        "{%0,%1,%2,%3}, {%4,%5,%6,%7}, {%8,%9}, {%0,%1,%2,%3};"
        : "+f"(c[0]), "+f"(c[1]), "+f"(c[2]), "+f"(c[3])
        : "r"(a[0]), "r"(a[1]), "r"(a[2]), "r"(a[3]), "r"(b[0]), "r"(b[1]));
}

// ---------------- kernel: bf16 HMMA distance GEMM ----------------------------
// d2[q][n] = x2[q] + t2[n] - 2 * dot_bf16(X[q], T[n])   (fp32 accumulate)
// CTA 128x128, BK=32, double-buffered smem, 8 warps: 4(m) x 2(n), warp tile 32x64.
#define BM 128
#define BN 128
#define BK 32
#define SROW 80                 // padded smem row: 40 bf16 (conflict-free frags)
#define ABYTES (BM * SROW)      // 10240
#define BBYTES (BN * SROW)

__global__ __launch_bounds__(256, 2) void dist_gemm_mma(int N, int Q)
{
    __shared__ __align__(16) char smA[2][ABYTES];
    __shared__ __align__(16) char smB[2][BBYTES];

    const int tid = threadIdx.x;
    const int wid = tid >> 5;
    const int lane = tid & 31;
    const int tq = lane >> 2, tr = lane & 3;
    const int wm = wid & 3, wn = wid >> 2;
    const int bq = blockIdx.y * BM, bn = blockIdx.x * BN;

    // g2s loader mapping: thread -> (row = tid>>2 [+64], seg = tid&3), uint4 = 8 bf16
    const int lrow = tid >> 2;
    const int lseg = tid & 3;
    const int kseg = lseg * 8;                 // bf16 offset in chunk
    const int ssm  = lrow * SROW + lseg * 16;  // smem byte offset (s=0)
    int ar0 = bq + lrow;        if (ar0 > Q - 1) ar0 = Q - 1;
    int ar1 = bq + lrow + 64;   if (ar1 > Q - 1) ar1 = Q - 1;
    const size_t aoff0 = (size_t)ar0 * D_DIM;
    const size_t aoff1 = (size_t)ar1 * D_DIM;
    const size_t boff0 = (size_t)(bn + lrow) * D_DIM;
    const size_t boff1 = (size_t)(bn + lrow + 64) * D_DIM;

    float c[2][8][4];
#pragma unroll
    for (int mi = 0; mi < 2; ++mi)
#pragma unroll
        for (int ni = 0; ni < 8; ++ni)
#pragma unroll
            for (int j = 0; j < 4; ++j) c[mi][ni][j] = 0.f;

    // prologue: chunk 0 -> buffer 0
    {
        uint4 a0 = *reinterpret_cast<const uint4*>(g_xb + aoff0 + kseg);
        uint4 a1 = *reinterpret_cast<const uint4*>(g_xb + aoff1 + kseg);
        uint4 b0 = *reinterpret_cast<const uint4*>(g_tb + boff0 + kseg);
        uint4 b1 = *reinterpret_cast<const uint4*>(g_tb + boff1 + kseg);
        *reinterpret_cast<uint4*>(smA[0] + ssm)             = a0;
        *reinterpret_cast<uint4*>(smA[0] + ssm + 64 * SROW) = a1;
        *reinterpret_cast<uint4*>(smB[0] + ssm)             = b0;
        *reinterpret_cast<uint4*>(smB[0] + ssm + 64 * SROW) = b1;
    }
    __syncthreads();

#pragma unroll 2
    for (int kc = 0; kc < D_DIM / BK; ++kc) {
        uint4 av0, av1, bv0, bv1;
        const bool pre = (kc + 1) < (D_DIM / BK);
        if (pre) {
            const int ko = (kc + 1) * BK + kseg;
            av0 = *reinterpret_cast<const uint4*>(g_xb + aoff0 + ko);
            av1 = *reinterpret_cast<const uint4*>(g_xb + aoff1 + ko);
            bv0 = *reinterpret_cast<const uint4*>(g_tb + boff0 + ko);
            bv1 = *reinterpret_cast<const uint4*>(g_tb + boff1 + ko);
        }
        const char* sA = smA[kc & 1];
        const char* sB = smB[kc & 1];
#pragma unroll
        for (int ks = 0; ks < 2; ++ks) {
            uint32_t a[2][4], b[8][2];
#pragma unroll
            for (int mi = 0; mi < 2; ++mi) {
                const char* p = sA + (wm * 32 + mi * 16 + tq) * SROW + ks * 32 + tr * 4;
                a[mi][0] = *reinterpret_cast<const uint32_t*>(p);
                a[mi][1] = *reinterpret_cast<const uint32_t*>(p + 8 * SROW);
                a[mi][2] = *reinterpret_cast<const uint32_t*>(p + 16);
                a[mi][3] = *reinterpret_cast<const uint32_t*>(p + 8 * SROW + 16);
            }
#pragma unroll
            for (int ni = 0; ni < 8; ++ni) {
                const char* p = sB + (wn * 64 + ni * 8 + tq) * SROW + ks * 32 + tr * 4;
                b[ni][0] = *reinterpret_cast<const uint32_t*>(p);
                b[ni][1] = *reinterpret_cast<const uint32_t*>(p + 16);
            }
#pragma unroll
            for (int mi = 0; mi < 2; ++mi)
#pragma unroll
                for (int ni = 0; ni < 8; ++ni)
                    mma16816(c[mi][ni], a[mi], b[ni]);
        }
        if (pre) {
            char* dA = smA[(kc + 1) & 1];
            char* dB = smB[(kc + 1) & 1];
            *reinterpret_cast<uint4*>(dA + ssm)             = av0;
            *reinterpret_cast<uint4*>(dA + ssm + 64 * SROW) = av1;
            *reinterpret_cast<uint4*>(dB + ssm)             = bv0;
            *reinterpret_cast<uint4*>(dB + ssm + 64 * SROW) = bv1;
        }
        __syncthreads();
    }

    // epilogue: d2 = x2 + t2 - 2*dot
#pragma unroll
    for (int mi = 0; mi < 2; ++mi) {
#pragma unroll
        for (int h = 0; h < 2; ++h) {          // h=0: rows g (c0,c1); h=1: rows g+8 (c2,c3)
            int q = bq + wm * 32 + mi * 16 + tq + h * 8;
            if (q >= Q) continue;
            float qn = g_x2[q];
            float* orow = g_d2 + (size_t)q * N;
#pragma unroll
            for (int ni = 0; ni < 8; ++ni) {
                int n0 = bn + wn * 64 + ni * 8 + tr * 2;
                if (n0 < N) {                   // N even, n0 even -> n0+1 also valid
                    float2 o;
                    o.x = qn + g_t2[n0 + 0] - 2.f * c[mi][ni][h * 2 + 0];
                    o.y = qn + g_t2[n0 + 1] - 2.f * c[mi][ni][h * 2 + 1];
                    *reinterpret_cast<float2*>(orow + n0) = o;
                }
            }
        }
    }
}

// ---------------- kernel: approx top-8/thread -> 64 candidates -> exact rerank
#define TKT 256

__global__ __launch_bounds__(TKT) void topk_rerank(
    const float* __restrict__ X, const float* __restrict__ T,
    const int* __restrict__ labels, float* __restrict__ out,
    int N, int Q, int out_size)
{
    const int q = blockIdx.x;
    const int tid = threadIdx.x;
    const int lane = tid & 31, wid = tid >> 5;
    const float* row = g_d2 + (size_t)q * N;

    float bd[8]; int bi[8];
#pragma unroll
    for (int j = 0; j < 8; ++j) { bd[j] = 3.4e38f; bi[j] = 0x7fffffff; }
    float thr = 3.4e38f;

    const float4* row4 = reinterpret_cast<const float4*>(row);
    const int n4 = N >> 2;
    for (int i = tid; i < n4; i += TKT) {
        float4 v = row4[i];
        float vv[4] = {v.x, v.y, v.z, v.w};
        int base = i << 2;
#pragma unroll
        for (int t = 0; t < 4; ++t) {
            if (vv[t] < thr) {
                float vd = vv[t]; int vi = base + t;
#pragma unroll
                for (int j = 0; j < 8; ++j)
                    if (vd < bd[j]) { float td = bd[j]; int ti = bi[j];
                                      bd[j] = vd; bi[j] = vi; vd = td; vi = ti; }
                thr = bd[7];
            }
        }
    }
    for (int n = (N & ~3) + tid; n < N; n += TKT) {
        float d = row[n];
        if (d < thr) {
            float vd = d; int vi = n;
#pragma unroll
            for (int j = 0; j < 8; ++j)
                if (vd < bd[j]) { float td = bd[j]; int ti = bi[j];
                                  bd[j] = vd; bi[j] = vi; vd = td; vi = ti; }
            thr = bd[7];
        }
    }

    __shared__ float sd[TKT * 8];
    __shared__ int   si[TKT * 8];
#pragma unroll
    for (int j = 0; j < 8; ++j) { sd[tid * 8 + j] = bd[j]; si[tid * 8 + j] = bi[j]; }
    __syncthreads();

    // stage 1: one thread per warp merges its warp's 256 entries -> warp top-8
    __shared__ float wdv[64];
    __shared__ int   wiv[64];
    if (lane == 0) {
        float md[8]; int mx[8];
#pragma unroll
        for (int j = 0; j < 8; ++j) { md[j] = 3.4e38f; mx[j] = 0x7fffffff; }
        float mthr = 3.4e38f;
        const int base = wid * 256;
        for (int t = 0; t < 256; ++t) {
            float d = sd[base + t];
            if (d < mthr) {
                float vd = d; int vi = si[base + t];
#pragma unroll
                for (int j = 0; j < 8; ++j)
                    if (vd < md[j]) { float td = md[j]; int ti = mx[j];
                                      md[j] = vd; mx[j] = vi; vd = td; vi = ti; }
                mthr = md[7];
            }
        }
#pragma unroll
        for (int j = 0; j < 8; ++j) { wdv[wid * 8 + j] = md[j]; wiv[wid * 8 + j] = mx[j]; }
    }
    __syncthreads();

    // exact fp32 rerank of the 64 candidates (warp wid -> candidates wid*8..+7)
    __shared__ float ed[64];
    {
        const float4* x4 = reinterpret_cast<const float4*>(X + (size_t)q * D_DIM);
        float4 xv[4];
#pragma unroll
        for (int j = 0; j < 4; ++j) xv[j] = x4[lane + j * 32];
        for (int cc = 0; cc < 8; ++cc) {
            int idx = wiv[wid * 8 + cc];
            float d2 = 3.4e38f;
            if (idx >= 0 && idx < N) {
                const float4* t4 = reinterpret_cast<const float4*>(T + (size_t)idx * D_DIM);
                float dot = 0.f;
#pragma unroll
                for (int j = 0; j < 4; ++j) {
                    float4 tv = t4[lane + j * 32];
                    dot += xv[j].x * tv.x + xv[j].y * tv.y + xv[j].z * tv.z + xv[j].w * tv.w;
                }
#pragma unroll
                for (int o = 16; o; o >>= 1) dot += __shfl_xor_sync(0xffffffffu, dot, o);
                d2 = g_x2[q] + g_t2[idx] - 2.f * dot;
            }
            if (lane == 0) ed[wid * 8 + cc] = d2;
        }
    }
    __syncthreads();

    // final exact top-5 with (d2, idx) tie-break; write all three output segments
    if (tid == 0) {
        float fd[5]; int fi[5];
#pragma unroll
        for (int j = 0; j < 5; ++j) { fd[j] = 3.4e38f; fi[j] = 0x7fffffff; }
        for (int t = 0; t < 64; ++t) {
            float vd = ed[t]; int vi = wiv[t];
#pragma unroll
            for (int j = 0; j < 5; ++j) {
                bool lt = (vd < fd[j]) || (vd == fd[j] && vi < fi[j]);
                if (lt) { float td = fd[j]; int ti = fi[j];
                          fd[j] = vd; fi[j] = vi; vd = td; vi = ti; }
            }
        }
        const int Q5 = Q * 5;
#pragma unroll
        for (int j = 0; j < 5; ++j) {
            float dist = sqrtf(fmaxf(fd[j], 0.f));
            int idx = fi[j];
            int o0 = q * 5 + j;
            int o1 = Q5 + q * 5 + j;
            int o2 = 2 * Q5 + j * Q + q;
            if (o0 < out_size) out[o0] = dist;
            if (o1 < out_size) out[o1] = (float)idx;
            if (o2 < out_size) out[o2] = (float)labels[idx];
        }
    }
}

// ---------------- launch -----------------------------------------------------
extern "C" void kernel_launch(void* const* d_in, const int* in_sizes, int n_in,
                              void* d_out, int out_size)
{
    const float* X      = (const float*)d_in[0];
    const float* T      = (const float*)d_in[1];
    const int*   labels = (const int*)d_in[2];
    const int Q = in_sizes[0] / D_DIM;
    const int N = in_sizes[2];

    // fused convert + norms (one pass over each matrix); pad T to NPAD with zeros
    convert_norm<<<(Q * 32 + 255) / 256, 256>>>(X, Q, Q, 0);
    convert_norm<<<(NPAD * 32 + 255) / 256, 256>>>(T, N, NPAD, 1);

    dim3 grid((N + BN - 1) / BN, (Q + BM - 1) / BM);
    dist_gemm_mma<<<grid, 256>>>(N, Q);

    topk_rerank<<<Q, TKT>>>(X, T, labels, (float*)d_out, N, Q, out_size);
}